// round 12
// baseline (speedup 1.0000x reference)
#include <cuda_runtime.h>
#include <cuda_bf16.h>

#define TT 4
#define EE 2048
#define PP 512
#define DE 16
#define DH 128
#define P1 508   // P-K+1
#define P2 504   // P-2K+2

typedef unsigned long long u64;

// ---------------- scratch (device globals) ----------------
__device__ float d_elem[TT * EE * DE];        // [t][e][16]
__device__ float d_s0p[TT * 32 * 16];         // s0 partials [t][chunk][16]
__device__ float d_g1[TT * EE * DH];          // [t][e][128] (L2-resident)
__device__ float d_s1p[TT * 128 * DH];        // s1 partials [t][chunk][128]
__device__ int   d_gmax[TT * DH];             // float bits, >= 0
__device__ float d_fpart[8 * 256];

// ---------------- helpers ----------------
__device__ __forceinline__ u64 pack2(float a, float b) {
    u64 r; asm("mov.b64 %0, {%1, %2};" : "=l"(r) : "f"(a), "f"(b)); return r;
}
__device__ __forceinline__ void unpack2(u64 v, float& a, float& b) {
    asm("mov.b64 {%0, %1}, %2;" : "=f"(a), "=f"(b) : "l"(v));
}
__device__ __forceinline__ void fma2(u64& d, u64 a, u64 b) {
    asm("fma.rn.f32x2 %0, %1, %2, %0;" : "+l"(d) : "l"(a), "l"(b));
}
// pack two floats to bf16x2 word: lo <- first arg, hi <- second
__device__ __forceinline__ unsigned cvt2(float lo, float hi) {
    unsigned r;
    asm("cvt.rn.bf16x2.f32 %0, %1, %2;" : "=r"(r) : "f"(hi), "f"(lo));
    return r;
}

// ---------------- bf16 mma m16n8k16 (A row, B col, fp32 acc) ----------------
__device__ __forceinline__ void mma_bf16(float* c,
    unsigned a0, unsigned a1, unsigned a2, unsigned a3,
    unsigned b0, unsigned b1)
{
    asm volatile(
        "mma.sync.aligned.m16n8k16.row.col.f32.bf16.bf16.f32 "
        "{%0,%1,%2,%3}, {%4,%5,%6,%7}, {%8,%9}, {%0,%1,%2,%3};"
        : "+f"(c[0]), "+f"(c[1]), "+f"(c[2]), "+f"(c[3])
        : "r"(a0), "r"(a1), "r"(a2), "r"(a3), "r"(b0), "r"(b1));
}

// ---------------- K1: conv1 (f32x2) + conv2 (bf16 HMMA split) ----------------
// grid (E, T), block 256 (8 warps: more latency hiding per SM)
__global__ __launch_bounds__(256) void k_conv(
    const float* __restrict__ points,
    const float* __restrict__ w1, const float* __restrict__ b1,
    const float* __restrict__ w2, const float* __restrict__ b2)
{
    // h1 transposed [p][ci], split big/residual bf16, row stride 18 bf16 (9 words)
    __shared__ __align__(16) __nv_bfloat16 h1b[520 * 18];
    __shared__ __align__(16) __nv_bfloat16 h1r[520 * 18];
    __shared__ float pts[2][PP];
    __shared__ __align__(4) __nv_bfloat16 w2b[1280];   // [(co*5+s)*16 + ci]
    __shared__ __align__(4) __nv_bfloat16 w2r[1280];
    __shared__ float w1s[160];
    __shared__ float b1s[16], b2s[16];
    __shared__ float redw[8][16];

    const int tid = threadIdx.x;
    const int t = blockIdx.y, e = blockIdx.x;

    unsigned* h1b32 = reinterpret_cast<unsigned*>(h1b);
    unsigned* h1r32 = reinterpret_cast<unsigned*>(h1r);

    // ---- stage inputs ----
    const float2* pin2 = reinterpret_cast<const float2*>(points + (size_t)(t * EE + e) * PP * 2);
    #pragma unroll
    for (int j = 0; j < 2; j++) {
        int p = tid + j * 256;
        float2 v = pin2[p];
        pts[0][p] = v.x; pts[1][p] = v.y;
    }
    if (tid < 160) w1s[tid] = w1[t * 160 + tid];
    // split W2 into bf16 big + residual, layout [(co*5+s)*16 + ci]
    #pragma unroll
    for (int i = tid; i < 1280; i += 256) {
        float v = w2[t * 1280 + i];
        int co = i / 80, rem = i % 80, ci = rem / 5, s = rem % 5;
        __nv_bfloat16 b = __float2bfloat16(v);
        float r = v - __bfloat162float(b);
        w2b[(co * 5 + s) * 16 + ci] = b;
        w2r[(co * 5 + s) * 16 + ci] = __float2bfloat16(r);
    }
    if (tid < 16) { b1s[tid] = b1[t * 16 + tid]; b2s[tid] = b2[t * 16 + tid]; }
    __syncthreads();

    // ---- conv1: one position pair per thread (pA=tid, pB=tid+256) ----
    const int pBc = (tid + 256 < P1) ? (tid + 256) : (P1 - 1);
    const bool m1 = (tid + 256 < P1);
    u64 xp[5], yp[5];
    #pragma unroll
    for (int k = 0; k < 5; k++) {
        xp[k] = pack2(pts[0][tid + k], pts[0][pBc + k]);
        yp[k] = pack2(pts[1][tid + k], pts[1][pBc + k]);
    }
    #pragma unroll 1
    for (int cp = 0; cp < 8; cp++) {
        float wA[10], wB[10];
        #pragma unroll
        for (int q = 0; q < 10; q++) {
            wA[q] = w1s[(2 * cp) * 10 + q];
            wB[q] = w1s[(2 * cp + 1) * 10 + q];
        }
        float bbA = b1s[2 * cp], bbB = b1s[2 * cp + 1];
        u64 aA = pack2(bbA, bbA);
        u64 aB = pack2(bbB, bbB);
        #pragma unroll
        for (int k = 0; k < 5; k++) {
            fma2(aA, pack2(wA[k], wA[k]), xp[k]);
            fma2(aB, pack2(wB[k], wB[k]), xp[k]);
        }
        #pragma unroll
        for (int k = 0; k < 5; k++) {
            fma2(aA, pack2(wA[5 + k], wA[5 + k]), yp[k]);
            fma2(aB, pack2(wB[5 + k], wB[5 + k]), yp[k]);
        }
        float vA[2], vB[2];
        unpack2(aA, vA[0], vA[1]);
        unpack2(aB, vB[0], vB[1]);
        // j = 0: position tid (always valid)
        {
            float a = fmaxf(vA[0], 0.f), b = fmaxf(vB[0], 0.f);
            unsigned big = cvt2(a, b);
            float loF = __int_as_float(big << 16);
            float hiF = __int_as_float(big & 0xffff0000u);
            unsigned res = cvt2(a - loF, b - hiF);
            h1b32[tid * 9 + cp] = big;
            h1r32[tid * 9 + cp] = res;
        }
        // j = 1: position tid+256 (masked)
        if (m1) {
            float a = fmaxf(vA[1], 0.f), b = fmaxf(vB[1], 0.f);
            unsigned big = cvt2(a, b);
            float loF = __int_as_float(big << 16);
            float hiF = __int_as_float(big & 0xffff0000u);
            unsigned res = cvt2(a - loF, b - hiF);
            h1b32[(tid + 256) * 9 + cp] = big;
            h1r32[(tid + 256) * 9 + cp] = res;
        }
    }
    __syncthreads();

    // ---- conv2 via bf16 HMMA: 8 warps, warp w handles nb = w + 8*i ----
    const int lane = tid & 31, wrp = tid >> 5;
    const int g = lane >> 2, tq = lane & 3;

    float acc[8][4];
    #pragma unroll
    for (int i = 0; i < 8; i++) {
        acc[i][0] = 0.f; acc[i][1] = 0.f; acc[i][2] = 0.f; acc[i][3] = 0.f;
    }

    const unsigned* w2b32 = reinterpret_cast<const unsigned*>(w2b);
    const unsigned* w2r32 = reinterpret_cast<const unsigned*>(w2r);

    #pragma unroll
    for (int s = 0; s < 5; s++) {
        const int awl = (g * 5 + s) * 8 + tq;
        const int awh = ((g + 8) * 5 + s) * 8 + tq;
        unsigned ab0 = w2b32[awl],     ab1 = w2b32[awh];
        unsigned ab2 = w2b32[awl + 4], ab3 = w2b32[awh + 4];
        unsigned ar0 = w2r32[awl],     ar1 = w2r32[awh];
        unsigned ar2 = w2r32[awl + 4], ar3 = w2r32[awh + 4];
        #pragma unroll
        for (int i = 0; i < 8; i++) {
            int nb = wrp + 8 * i;
            if (nb >= 63) break;
            int pw = (nb * 8 + g + s) * 9 + tq;
            unsigned bb0 = h1b32[pw], bb1 = h1b32[pw + 4];
            unsigned br0 = h1r32[pw], br1 = h1r32[pw + 4];
            mma_bf16(acc[i], ab0, ab1, ab2, ab3, bb0, bb1);
            mma_bf16(acc[i], ab0, ab1, ab2, ab3, br0, br1);
            mma_bf16(acc[i], ar0, ar1, ar2, ar3, bb0, bb1);
        }
    }

    // ---- epilogue: bias + relu per position, point-sum ----
    const float b2g = b2s[g], b2g8 = b2s[g + 8];
    float sg = 0.f, sg8 = 0.f;
    #pragma unroll
    for (int i = 0; i < 8; i++) {
        int nb = wrp + 8 * i;
        if (nb >= 63) break;
        sg  += fmaxf(acc[i][0] + b2g, 0.f)  + fmaxf(acc[i][1] + b2g, 0.f);
        sg8 += fmaxf(acc[i][2] + b2g8, 0.f) + fmaxf(acc[i][3] + b2g8, 0.f);
    }
    sg  += __shfl_xor_sync(0xffffffffu, sg, 1);
    sg  += __shfl_xor_sync(0xffffffffu, sg, 2);
    sg8 += __shfl_xor_sync(0xffffffffu, sg8, 1);
    sg8 += __shfl_xor_sync(0xffffffffu, sg8, 2);
    if (tq == 0) { redw[wrp][g] = sg; redw[wrp][g + 8] = sg8; }
    __syncthreads();
    if (tid < 16) {
        float s = 0.f;
        #pragma unroll
        for (int w = 0; w < 8; w++) s += redw[w][tid];
        d_elem[(size_t)(t * EE + e) * 16 + tid] = s;
    }
}

// ---------------- K2: s0 partials (+zero gmax)  grid (32, T), block 256 ----------------
__global__ __launch_bounds__(256) void k_s0p() {
    const int t = blockIdx.y, chunk = blockIdx.x, tid = threadIdx.x;
    const int d = tid & 15, grp = tid >> 4;   // 16 groups x 4 e's
    const int e0 = chunk * 64;
    float acc = 0.f;
    #pragma unroll
    for (int i = 0; i < 4; i++)
        acc += d_elem[(size_t)(t * EE + e0 + grp + 16 * i) * 16 + d];
    __shared__ float r[256];
    r[tid] = acc; __syncthreads();
    if (tid < 128) r[tid] += r[tid + 128];
    __syncthreads();
    if (tid < 64) r[tid] += r[tid + 64];
    __syncthreads();
    if (tid < 32) r[tid] += r[tid + 32];
    __syncthreads();
    if (tid < 16) d_s0p[(t * 32 + chunk) * 16 + tid] = r[tid] + r[tid + 16];
    if (chunk == 0 && tid < 128) d_gmax[t * 128 + tid] = 0;
}

// ---------------- K3: layer1 -> d_g1 + s1 partials  grid (128, T), block 256 ----------------
__global__ __launch_bounds__(256) void k_l1(
    const float* __restrict__ A1, const float* __restrict__ B1)
{
    __shared__ float C1s[16][128];
    __shared__ float elems[16][16];
    __shared__ float r[256];
    __shared__ float s0s[16];

    const int tid = threadIdx.x, t = blockIdx.y, chunk = blockIdx.x;
    const int e0 = chunk * 16;
    const int h = tid & 127, half = tid >> 7;

    elems[tid >> 4][tid & 15] = d_elem[(size_t)(t * EE + e0) * 16 + tid];
    for (int i = tid; i < 2048; i += 256)
        C1s[i >> 7][i & 127] = A1[t * 2048 + i] - B1[t * 2048 + i];
    if (tid < 16) {
        float s = 0.f;
        #pragma unroll
        for (int b = 0; b < 32; b++) s += d_s0p[(t * 32 + b) * 16 + tid];
        s0s[tid] = s;
    }
    __syncthreads();

    float c1r[16];
    #pragma unroll
    for (int d = 0; d < 16; d++) c1r[d] = C1s[d][h];
    float sbl1 = 0.f;
    #pragma unroll
    for (int d = 0; d < 16; d++)
        sbl1 = fmaf(s0s[d], B1[t * 2048 + d * 128 + h], sbl1);

    float accs = 0.f;
    const int eib = half * 8;
    #pragma unroll
    for (int ei = 0; ei < 8; ei++) {
        float v = sbl1;
        #pragma unroll
        for (int d = 0; d < 16; d++) v = fmaf(elems[eib + ei][d], c1r[d], v);
        v = fmaxf(v, 0.f);
        d_g1[(size_t)(t * EE + e0 + eib + ei) * 128 + h] = v;
        accs += v;
    }
    r[tid] = accs;
    __syncthreads();
    if (tid < 128)
        d_s1p[(t * 128 + chunk) * 128 + tid] = r[tid] + r[tid + 128];
}

// ---------------- K4: layer2 GEMM + max  grid (64, T), block 256 (32 e's/block) ----------------
__global__ __launch_bounds__(256) void k_l2(
    const float* __restrict__ A2, const float* __restrict__ B2)
{
    __shared__ __align__(8) float g1T[128][34];   // [feature d][ei 0..31]
    __shared__ float C2q[2][16][128];
    __shared__ float r[256];
    __shared__ float s1s[128];

    const int tid = threadIdx.x, t = blockIdx.y, chunk = blockIdx.x;
    const int e0 = chunk * 32;
    const int h = tid & 127, half = tid >> 7;
    const int tb = t * 16384;

    // prefetch first C2 slab early
    float pa_[8], pb_[8];
    #pragma unroll
    for (int k = 0; k < 8; k++) {
        int idx = tid + k * 256;
        pa_[k] = A2[tb + idx];
        pb_[k] = B2[tb + idx];
    }

    // s1 combine (128 partials, 64 per half)
    {
        float a = 0.f;
        #pragma unroll 4
        for (int s = 0; s < 64; s++)
            a += d_s1p[(t * 128 + half * 64 + s) * 128 + h];
        r[tid] = a;
    }

    // g1 tile load (transposed into smem)
    for (int i = tid; i < 4096; i += 256) {
        int ei = i >> 7, hh = i & 127;
        g1T[hh][ei] = d_g1[(size_t)(t * EE + e0 + ei) * 128 + hh];
    }
    __syncthreads();
    if (tid < 128) s1s[tid] = r[tid] + r[tid + 128];
    __syncthreads();

    u64 acc2[8];
    #pragma unroll
    for (int pr = 0; pr < 8; pr++) acc2[pr] = 0ull;
    float sbp = 0.f;

    #pragma unroll 1
    for (int q = 0; q < 8; q++) {
        const int buf = q & 1;
        #pragma unroll
        for (int k = 0; k < 8; k++) {
            int d = 2 * k + half;
            sbp = fmaf(s1s[q * 16 + d], pb_[k], sbp);
            C2q[buf][d][h] = pa_[k] - pb_[k];
        }
        __syncthreads();
        if (q < 7) {
            const int base = tb + (q + 1) * 16 * 128;
            #pragma unroll
            for (int k = 0; k < 8; k++) {
                int idx = tid + k * 256;
                pa_[k] = A2[base + idx];
                pb_[k] = B2[base + idx];
            }
        }
        #pragma unroll 4
        for (int dd = 0; dd < 16; dd++) {
            float c = C2q[buf][dd][h];
            u64 cp = pack2(c, c);
            const u64* grow = reinterpret_cast<const u64*>(&g1T[q * 16 + dd][half * 16]);
            #pragma unroll
            for (int pr = 0; pr < 8; pr++) fma2(acc2[pr], grow[pr], cp);
        }
        __syncthreads();
    }

    // combine sb halves (even/odd d parity)
    r[tid] = sbp;
    __syncthreads();
    const float sb = r[h] + r[h + 128];

    float m = 0.f;   // relu floor == max identity
    #pragma unroll
    for (int pr = 0; pr < 8; pr++) {
        float a, b;
        unpack2(acc2[pr], a, b);
        m = fmaxf(m, fmaxf(a + sb, b + sb));
    }
    atomicMax(&d_gmax[t * 128 + h], __float_as_int(m));
}

// ---------------- K5: gf + final matmul partials  grid 8, block 256 ----------------
__global__ __launch_bounds__(256) void k_gfw(const float* __restrict__ Aout,
                                             const float* __restrict__ Wm)
{
    __shared__ float gv[512];
    __shared__ float gfs[64];
    __shared__ float r[256];
    const int tid = threadIdx.x, blk = blockIdx.x;

    for (int i = tid; i < 512; i += 256) gv[i] = __int_as_float(d_gmax[i]);
    __syncthreads();

    const int j = tid >> 2, sub = tid & 3;
    const int gi = blk * 64 + j;          // global gf index = t*128 + o
    const int t2 = gi >> 7, o = gi & 127;
    float a = 0.f;
    #pragma unroll 4
    for (int k = 0; k < 32; k++)
        a = fmaf(gv[t2 * 128 + sub * 32 + k],
                 Aout[t2 * 16384 + (sub * 32 + k) * 128 + o], a);
    r[tid] = a;
    __syncthreads();
    if (sub == 0) gfs[j] = r[tid] + r[tid + 1] + r[tid + 2] + r[tid + 3];
    __syncthreads();

    float acc = 0.f;
    const int i0 = blk * 64;
    #pragma unroll 8
    for (int i = 0; i < 64; i++)
        acc = fmaf(gfs[i], Wm[(i0 + i) * 256 + tid], acc);
    d_fpart[blk * 256 + tid] = acc;
}

// ---------------- K6: combine  grid 1, block 256 ----------------
__global__ void k_fin2(const float* __restrict__ bm, float* __restrict__ out) {
    const int tid = threadIdx.x;
    float a = bm[tid];
    #pragma unroll
    for (int b = 0; b < 8; b++) a += d_fpart[b * 256 + tid];
    out[tid] = a;
}

// ---------------- launch ----------------
extern "C" void kernel_launch(void* const* d_in, const int* in_sizes, int n_in,
                              void* d_out, int out_size)
{
    const float* points = (const float*)d_in[0];
    const float* w1     = (const float*)d_in[1];
    const float* b1     = (const float*)d_in[2];
    const float* w2     = (const float*)d_in[3];
    const float* b2     = (const float*)d_in[4];
    const float* A1     = (const float*)d_in[5];
    const float* B1     = (const float*)d_in[6];
    const float* A2     = (const float*)d_in[7];
    const float* B2     = (const float*)d_in[8];
    const float* Aout   = (const float*)d_in[9];
    const float* Wm     = (const float*)d_in[10];
    const float* bm     = (const float*)d_in[11];
    float* out = (float*)d_out;

    k_conv<<<dim3(EE, TT), 256>>>(points, w1, b1, w2, b2);
    k_s0p<<<dim3(32, TT), 256>>>();
    k_l1<<<dim3(128, TT), 256>>>(A1, B1);
    k_l2<<<dim3(64, TT), 256>>>(A2, B2);
    k_gfw<<<8, 256>>>(Aout, Wm);
    k_fin2<<<1, 256>>>(bm, out);
}

// round 13
// speedup vs baseline: 1.1437x; 1.1437x over previous
#include <cuda_runtime.h>
#include <cuda_bf16.h>

#define TT 4
#define EE 2048
#define PP 512
#define DE 16
#define DH 128
#define P1 508   // P-K+1
#define P2 504   // P-2K+2

typedef unsigned long long u64;

// ---------------- scratch (device globals) ----------------
__device__ float d_elem[TT * EE * DE];        // [t][e][16]
__device__ float d_s0p[TT * 32 * 16];         // s0 partials [t][chunk][16]
__device__ float d_g1[TT * EE * DH];          // [t][e][128] (L2-resident)
__device__ float d_s1p[TT * 128 * DH];        // s1 partials [t][chunk][128]
__device__ float d_s1[TT * DH];               // combined s1
__device__ int   d_gmax[TT * DH];             // float bits, >= 0
__device__ float d_fpart[8 * 256];

// ---------------- helpers ----------------
__device__ __forceinline__ u64 pack2(float a, float b) {
    u64 r; asm("mov.b64 %0, {%1, %2};" : "=l"(r) : "f"(a), "f"(b)); return r;
}
__device__ __forceinline__ void unpack2(u64 v, float& a, float& b) {
    asm("mov.b64 {%0, %1}, %2;" : "=f"(a), "=f"(b) : "l"(v));
}
__device__ __forceinline__ void fma2(u64& d, u64 a, u64 b) {
    asm("fma.rn.f32x2 %0, %1, %2, %0;" : "+l"(d) : "l"(a), "l"(b));
}
// pack two floats to bf16x2 word: lo <- first arg, hi <- second
__device__ __forceinline__ unsigned cvt2(float lo, float hi) {
    unsigned r;
    asm("cvt.rn.bf16x2.f32 %0, %1, %2;" : "=r"(r) : "f"(hi), "f"(lo));
    return r;
}

// ---------------- bf16 mma m16n8k16 (A row, B col, fp32 acc) ----------------
__device__ __forceinline__ void mma_bf16(float* c,
    unsigned a0, unsigned a1, unsigned a2, unsigned a3,
    unsigned b0, unsigned b1)
{
    asm volatile(
        "mma.sync.aligned.m16n8k16.row.col.f32.bf16.bf16.f32 "
        "{%0,%1,%2,%3}, {%4,%5,%6,%7}, {%8,%9}, {%0,%1,%2,%3};"
        : "+f"(c[0]), "+f"(c[1]), "+f"(c[2]), "+f"(c[3])
        : "r"(a0), "r"(a1), "r"(a2), "r"(a3), "r"(b0), "r"(b1));
}

// ---------------- K1: conv1 (f32x2) + conv2 (bf16 HMMA split), 2 e's per CTA ----------------
// grid (E/2, T), block 128 (R11 structure; weights staged once for both e's)
__global__ __launch_bounds__(128) void k_conv(
    const float* __restrict__ points,
    const float* __restrict__ w1, const float* __restrict__ b1,
    const float* __restrict__ w2, const float* __restrict__ b2)
{
    // h1 transposed [p][ci], split big/residual bf16, row stride 18 bf16 (9 words)
    __shared__ __align__(16) __nv_bfloat16 h1b[520 * 18];
    __shared__ __align__(16) __nv_bfloat16 h1r[520 * 18];
    __shared__ float pts[2][PP];
    __shared__ __align__(4) __nv_bfloat16 w2b[1280];   // [(co*5+s)*16 + ci]
    __shared__ __align__(4) __nv_bfloat16 w2r[1280];
    __shared__ float w1s[160];
    __shared__ float b1s[16], b2s[16];
    __shared__ float redw[4][16];

    const int tid = threadIdx.x;
    const int t = blockIdx.y, e0 = blockIdx.x * 2;

    unsigned* h1b32 = reinterpret_cast<unsigned*>(h1b);
    unsigned* h1r32 = reinterpret_cast<unsigned*>(h1r);

    // ---- stage weights (once per CTA) + pts(e0) ----
    const float2* pin2 = reinterpret_cast<const float2*>(points + (size_t)(t * EE + e0) * PP * 2);
    #pragma unroll
    for (int j = 0; j < 4; j++) {
        int p = tid + j * 128;
        float2 v = pin2[p];
        pts[0][p] = v.x; pts[1][p] = v.y;
    }
    for (int i = tid; i < 160; i += 128) w1s[i] = w1[t * 160 + i];
    for (int i = tid; i < 1280; i += 128) {
        float v = w2[t * 1280 + i];
        int co = i / 80, rem = i % 80, ci = rem / 5, s = rem % 5;
        __nv_bfloat16 b = __float2bfloat16(v);
        float r = v - __bfloat162float(b);
        w2b[(co * 5 + s) * 16 + ci] = b;
        w2r[(co * 5 + s) * 16 + ci] = __float2bfloat16(r);
    }
    if (tid < 16) { b1s[tid] = b1[t * 16 + tid]; b2s[tid] = b2[t * 16 + tid]; }
    __syncthreads();

    const int lane = tid & 31, wrp = tid >> 5;
    const int g = lane >> 2, tq = lane & 3;
    const float b2g = b2s[g], b2g8 = b2s[g + 8];

    #pragma unroll 1
    for (int sub = 0; sub < 2; sub++) {
        // ---- conv1 (packed f32x2, position pairs, co-pairs) -> h1 split words ----
        u64 xp[2][5], yp[2][5];
        #pragma unroll
        for (int pr = 0; pr < 2; pr++) {
            int pA = tid + (2 * pr) * 128;
            int pB = tid + (2 * pr + 1) * 128;
            int pAc = (pA < P1) ? pA : (P1 - 1);
            int pBc = (pB < P1) ? pB : (P1 - 1);
            #pragma unroll
            for (int k = 0; k < 5; k++) {
                xp[pr][k] = pack2(pts[0][pAc + k], pts[0][pBc + k]);
                yp[pr][k] = pack2(pts[1][pAc + k], pts[1][pBc + k]);
            }
        }
        // prefetch next e's points into regs (overlaps conv1 math)
        float2 pv[4];
        if (sub == 0) {
            const float2* pin2b = reinterpret_cast<const float2*>(
                points + (size_t)(t * EE + e0 + 1) * PP * 2);
            #pragma unroll
            for (int j = 0; j < 4; j++) pv[j] = pin2b[tid + j * 128];
        }

        const bool m1 = (tid + 384 < P1);
        #pragma unroll 1
        for (int cp = 0; cp < 8; cp++) {
            float wA[10], wB[10];
            #pragma unroll
            for (int q = 0; q < 10; q++) {
                wA[q] = w1s[(2 * cp) * 10 + q];
                wB[q] = w1s[(2 * cp + 1) * 10 + q];
            }
            float bbA = b1s[2 * cp], bbB = b1s[2 * cp + 1];
            u64 aA0 = pack2(bbA, bbA), aA1 = aA0;
            u64 aB0 = pack2(bbB, bbB), aB1 = aB0;
            #pragma unroll
            for (int k = 0; k < 5; k++) {
                u64 wa = pack2(wA[k], wA[k]);
                fma2(aA0, wa, xp[0][k]); fma2(aA1, wa, xp[1][k]);
                u64 wb = pack2(wB[k], wB[k]);
                fma2(aB0, wb, xp[0][k]); fma2(aB1, wb, xp[1][k]);
            }
            #pragma unroll
            for (int k = 0; k < 5; k++) {
                u64 wa = pack2(wA[5 + k], wA[5 + k]);
                fma2(aA0, wa, yp[0][k]); fma2(aA1, wa, yp[1][k]);
                u64 wb = pack2(wB[5 + k], wB[5 + k]);
                fma2(aB0, wb, yp[0][k]); fma2(aB1, wb, yp[1][k]);
            }
            float vA[4], vB[4];
            unpack2(aA0, vA[0], vA[1]); unpack2(aA1, vA[2], vA[3]);
            unpack2(aB0, vB[0], vB[1]); unpack2(aB1, vB[2], vB[3]);
            #pragma unroll
            for (int j = 0; j < 4; j++) {
                if (j == 3 && !m1) break;
                int p = tid + j * 128;
                float a = fmaxf(vA[j], 0.f), b = fmaxf(vB[j], 0.f);
                unsigned big = cvt2(a, b);
                float loF = __int_as_float(big << 16);
                float hiF = __int_as_float(big & 0xffff0000u);
                unsigned res = cvt2(a - loF, b - hiF);
                h1b32[p * 9 + cp] = big;
                h1r32[p * 9 + cp] = res;
            }
        }
        __syncthreads();   // h1 ready; all pts reads complete

        // commit prefetched next-e points (safe: pts reads done)
        if (sub == 0) {
            #pragma unroll
            for (int j = 0; j < 4; j++) {
                int p = tid + j * 128;
                pts[0][p] = pv[j].x; pts[1][p] = pv[j].y;
            }
        }

        // ---- conv2 via bf16 HMMA ----
        float acc[16][4];
        #pragma unroll
        for (int i = 0; i < 16; i++) {
            acc[i][0] = 0.f; acc[i][1] = 0.f; acc[i][2] = 0.f; acc[i][3] = 0.f;
        }
        const unsigned* w2b32 = reinterpret_cast<const unsigned*>(w2b);
        const unsigned* w2r32 = reinterpret_cast<const unsigned*>(w2r);

        #pragma unroll
        for (int s = 0; s < 5; s++) {
            const int awl = (g * 5 + s) * 8 + tq;
            const int awh = ((g + 8) * 5 + s) * 8 + tq;
            unsigned ab0 = w2b32[awl],     ab1 = w2b32[awh];
            unsigned ab2 = w2b32[awl + 4], ab3 = w2b32[awh + 4];
            unsigned ar0 = w2r32[awl],     ar1 = w2r32[awh];
            unsigned ar2 = w2r32[awl + 4], ar3 = w2r32[awh + 4];
            #pragma unroll
            for (int i = 0; i < 16; i++) {
                int nb = wrp + 4 * i;
                if (nb >= 63) break;
                int pw = (nb * 8 + g + s) * 9 + tq;
                unsigned bb0 = h1b32[pw], bb1 = h1b32[pw + 4];
                unsigned br0 = h1r32[pw], br1 = h1r32[pw + 4];
                mma_bf16(acc[i], ab0, ab1, ab2, ab3, bb0, bb1);
                mma_bf16(acc[i], ab0, ab1, ab2, ab3, br0, br1);
                mma_bf16(acc[i], ar0, ar1, ar2, ar3, bb0, bb1);
            }
        }

        // ---- epilogue: bias + relu per position, point-sum ----
        float sg = 0.f, sg8 = 0.f;
        #pragma unroll
        for (int i = 0; i < 16; i++) {
            int nb = wrp + 4 * i;
            if (nb >= 63) break;
            sg  += fmaxf(acc[i][0] + b2g, 0.f)  + fmaxf(acc[i][1] + b2g, 0.f);
            sg8 += fmaxf(acc[i][2] + b2g8, 0.f) + fmaxf(acc[i][3] + b2g8, 0.f);
        }
        sg  += __shfl_xor_sync(0xffffffffu, sg, 1);
        sg  += __shfl_xor_sync(0xffffffffu, sg, 2);
        sg8 += __shfl_xor_sync(0xffffffffu, sg8, 1);
        sg8 += __shfl_xor_sync(0xffffffffu, sg8, 2);
        if (tq == 0) { redw[wrp][g] = sg; redw[wrp][g + 8] = sg8; }
        __syncthreads();   // redw ready; conv2 done reading h1; pts(e1) visible
        if (tid < 16)
            d_elem[(size_t)(t * EE + e0 + sub) * 16 + tid] =
                redw[0][tid] + redw[1][tid] + redw[2][tid] + redw[3][tid];
    }
}

// ---------------- K2: s0 partials (+zero gmax)  grid (32, T), block 256 ----------------
__global__ __launch_bounds__(256) void k_s0p() {
    const int t = blockIdx.y, chunk = blockIdx.x, tid = threadIdx.x;
    const int d = tid & 15, grp = tid >> 4;   // 16 groups x 4 e's
    const int e0 = chunk * 64;
    float acc = 0.f;
    #pragma unroll
    for (int i = 0; i < 4; i++)
        acc += d_elem[(size_t)(t * EE + e0 + grp + 16 * i) * 16 + d];
    __shared__ float r[256];
    r[tid] = acc; __syncthreads();
    if (tid < 128) r[tid] += r[tid + 128];
    __syncthreads();
    if (tid < 64) r[tid] += r[tid + 64];
    __syncthreads();
    if (tid < 32) r[tid] += r[tid + 32];
    __syncthreads();
    if (tid < 16) d_s0p[(t * 32 + chunk) * 16 + tid] = r[tid] + r[tid + 16];
    if (chunk == 0 && tid < 128) d_gmax[t * 128 + tid] = 0;
}

// ---------------- K3: layer1 -> d_g1 + s1 partials  grid (128, T), block 256 ----------------
__global__ __launch_bounds__(256) void k_l1(
    const float* __restrict__ A1, const float* __restrict__ B1)
{
    __shared__ float C1s[16][128];
    __shared__ float elems[16][16];
    __shared__ float r[256];
    __shared__ float s0s[16];

    const int tid = threadIdx.x, t = blockIdx.y, chunk = blockIdx.x;
    const int e0 = chunk * 16;
    const int h = tid & 127, half = tid >> 7;

    elems[tid >> 4][tid & 15] = d_elem[(size_t)(t * EE + e0) * 16 + tid];
    for (int i = tid; i < 2048; i += 256)
        C1s[i >> 7][i & 127] = A1[t * 2048 + i] - B1[t * 2048 + i];
    if (tid < 16) {
        float s = 0.f;
        #pragma unroll
        for (int b = 0; b < 32; b++) s += d_s0p[(t * 32 + b) * 16 + tid];
        s0s[tid] = s;
    }
    __syncthreads();

    float c1r[16];
    #pragma unroll
    for (int d = 0; d < 16; d++) c1r[d] = C1s[d][h];
    float sbl1 = 0.f;
    #pragma unroll
    for (int d = 0; d < 16; d++)
        sbl1 = fmaf(s0s[d], B1[t * 2048 + d * 128 + h], sbl1);

    float accs = 0.f;
    const int eib = half * 8;
    #pragma unroll
    for (int ei = 0; ei < 8; ei++) {
        float v = sbl1;
        #pragma unroll
        for (int d = 0; d < 16; d++) v = fmaf(elems[eib + ei][d], c1r[d], v);
        v = fmaxf(v, 0.f);
        d_g1[(size_t)(t * EE + e0 + eib + ei) * 128 + h] = v;
        accs += v;
    }
    r[tid] = accs;
    __syncthreads();
    if (tid < 128)
        d_s1p[(t * 128 + chunk) * 128 + tid] = r[tid] + r[tid + 128];
}

// ---------------- K3b: combine s1 partials  grid (T), block 512 ----------------
__global__ __launch_bounds__(512) void k_s1c() {
    const int t = blockIdx.x, tid = threadIdx.x;
    const int h = tid & 127, q = tid >> 7;   // 4 groups x 32 partials
    float s = 0.f;
    #pragma unroll 8
    for (int i = 0; i < 32; i++)
        s += d_s1p[(t * 128 + q * 32 + i) * 128 + h];
    __shared__ float r[512];
    r[tid] = s; __syncthreads();
    if (tid < 128)
        d_s1[t * 128 + tid] = r[tid] + r[tid + 128] + r[tid + 256] + r[tid + 384];
}

// ---------------- K4: layer2 GEMM + max  grid (64, T), block 256 (32 e's/block) ----------------
__global__ __launch_bounds__(256) void k_l2(
    const float* __restrict__ A2, const float* __restrict__ B2)
{
    __shared__ __align__(8) float g1T[128][34];   // [feature d][ei 0..31]
    __shared__ float C2q[2][16][128];
    __shared__ float r[256];
    __shared__ float s1s[128];

    const int tid = threadIdx.x, t = blockIdx.y, chunk = blockIdx.x;
    const int e0 = chunk * 32;
    const int h = tid & 127, half = tid >> 7;
    const int tb = t * 16384;

    // prefetch first C2 slab early
    float pa_[8], pb_[8];
    #pragma unroll
    for (int k = 0; k < 8; k++) {
        int idx = tid + k * 256;
        pa_[k] = A2[tb + idx];
        pb_[k] = B2[tb + idx];
    }

    // s1 (pre-combined)
    if (tid < 128) s1s[tid] = d_s1[t * 128 + tid];

    // g1 tile load (transposed into smem)
    for (int i = tid; i < 4096; i += 256) {
        int ei = i >> 7, hh = i & 127;
        g1T[hh][ei] = d_g1[(size_t)(t * EE + e0 + ei) * 128 + hh];
    }
    __syncthreads();

    u64 acc2[8];
    #pragma unroll
    for (int pr = 0; pr < 8; pr++) acc2[pr] = 0ull;
    float sbp = 0.f;

    #pragma unroll 1
    for (int q = 0; q < 8; q++) {
        const int buf = q & 1;
        #pragma unroll
        for (int k = 0; k < 8; k++) {
            int d = 2 * k + half;
            sbp = fmaf(s1s[q * 16 + d], pb_[k], sbp);
            C2q[buf][d][h] = pa_[k] - pb_[k];
        }
        __syncthreads();
        if (q < 7) {
            const int base = tb + (q + 1) * 16 * 128;
            #pragma unroll
            for (int k = 0; k < 8; k++) {
                int idx = tid + k * 256;
                pa_[k] = A2[base + idx];
                pb_[k] = B2[base + idx];
            }
        }
        #pragma unroll 4
        for (int dd = 0; dd < 16; dd++) {
            float c = C2q[buf][dd][h];
            u64 cp = pack2(c, c);
            const u64* grow = reinterpret_cast<const u64*>(&g1T[q * 16 + dd][half * 16]);
            #pragma unroll
            for (int pr = 0; pr < 8; pr++) fma2(acc2[pr], grow[pr], cp);
        }
        __syncthreads();
    }

    // combine sb halves (even/odd d parity)
    r[tid] = sbp;
    __syncthreads();
    const float sb = r[h] + r[h + 128];

    float m = 0.f;   // relu floor == max identity
    #pragma unroll
    for (int pr = 0; pr < 8; pr++) {
        float a, b;
        unpack2(acc2[pr], a, b);
        m = fmaxf(m, fmaxf(a + sb, b + sb));
    }
    atomicMax(&d_gmax[t * 128 + h], __float_as_int(m));
}

// ---------------- K5: gf + final matmul partials  grid 8, block 256 ----------------
__global__ __launch_bounds__(256) void k_gfw(const float* __restrict__ Aout,
                                             const float* __restrict__ Wm)
{
    __shared__ float gv[512];
    __shared__ float gfs[64];
    __shared__ float r[256];
    const int tid = threadIdx.x, blk = blockIdx.x;

    for (int i = tid; i < 512; i += 256) gv[i] = __int_as_float(d_gmax[i]);
    __syncthreads();

    const int j = tid >> 2, sub = tid & 3;
    const int gi = blk * 64 + j;          // global gf index = t*128 + o
    const int t2 = gi >> 7, o = gi & 127;
    float a = 0.f;
    #pragma unroll 4
    for (int k = 0; k < 32; k++)
        a = fmaf(gv[t2 * 128 + sub * 32 + k],
                 Aout[t2 * 16384 + (sub * 32 + k) * 128 + o], a);
    r[tid] = a;
    __syncthreads();
    if (sub == 0) gfs[j] = r[tid] + r[tid + 1] + r[tid + 2] + r[tid + 3];
    __syncthreads();

    float acc = 0.f;
    const int i0 = blk * 64;
    #pragma unroll 8
    for (int i = 0; i < 64; i++)
        acc = fmaf(gfs[i], Wm[(i0 + i) * 256 + tid], acc);
    d_fpart[blk * 256 + tid] = acc;
}

// ---------------- K6: combine  grid 1, block 256 ----------------
__global__ void k_fin2(const float* __restrict__ bm, float* __restrict__ out) {
    const int tid = threadIdx.x;
    float a = bm[tid];
    #pragma unroll
    for (int b = 0; b < 8; b++) a += d_fpart[b * 256 + tid];
    out[tid] = a;
}

// ---------------- launch ----------------
extern "C" void kernel_launch(void* const* d_in, const int* in_sizes, int n_in,
                              void* d_out, int out_size)
{
    const float* points = (const float*)d_in[0];
    const float* w1     = (const float*)d_in[1];
    const float* b1     = (const float*)d_in[2];
    const float* w2     = (const float*)d_in[3];
    const float* b2     = (const float*)d_in[4];
    const float* A1     = (const float*)d_in[5];
    const float* B1     = (const float*)d_in[6];
    const float* A2     = (const float*)d_in[7];
    const float* B2     = (const float*)d_in[8];
    const float* Aout   = (const float*)d_in[9];
    const float* Wm     = (const float*)d_in[10];
    const float* bm     = (const float*)d_in[11];
    float* out = (float*)d_out;

    k_conv<<<dim3(EE / 2, TT), 128>>>(points, w1, b1, w2, b2);
    k_s0p<<<dim3(32, TT), 256>>>();
    k_l1<<<dim3(128, TT), 256>>>(A1, B1);
    k_s1c<<<TT, 512>>>();
    k_l2<<<dim3(64, TT), 256>>>(A2, B2);
    k_gfw<<<8, 256>>>(Aout, Wm);
    k_fin2<<<1, 256>>>(bm, out);
}

// round 14
// speedup vs baseline: 1.4297x; 1.2500x over previous
#include <cuda_runtime.h>
#include <cuda_bf16.h>
#include <cuda_fp16.h>

#define TT 4
#define EE 2048
#define PP 512
#define DE 16
#define DH 128
#define P1 508   // P-K+1
#define P2 504   // P-2K+2

typedef unsigned long long u64;

// ---------------- scratch (device globals) ----------------
__device__ float d_elem[TT * EE * DE];        // [t][e][16]
__device__ float d_s0p[TT * 32 * 16];         // s0 partials [t][chunk][16]
__device__ float d_g1[TT * EE * DH];          // [t][e][128] (L2-resident)
__device__ float d_s1p[TT * 128 * DH];        // s1 partials [t][chunk][128]
__device__ float d_s1[TT * DH];               // combined s1
__device__ int   d_gmax[TT * DH];             // float bits, >= 0
__device__ float d_fpart[8 * 256];

// ---------------- helpers ----------------
__device__ __forceinline__ u64 pack2(float a, float b) {
    u64 r; asm("mov.b64 %0, {%1, %2};" : "=l"(r) : "f"(a), "f"(b)); return r;
}
__device__ __forceinline__ void unpack2(u64 v, float& a, float& b) {
    asm("mov.b64 {%0, %1}, %2;" : "=f"(a), "=f"(b) : "l"(v));
}
__device__ __forceinline__ void fma2(u64& d, u64 a, u64 b) {
    asm("fma.rn.f32x2 %0, %1, %2, %0;" : "+l"(d) : "l"(a), "l"(b));
}

// ---------------- fp16 mma m16n8k16 (A row, B col, fp32 acc) ----------------
__device__ __forceinline__ void mma_f16(float* c,
    unsigned a0, unsigned a1, unsigned a2, unsigned a3,
    unsigned b0, unsigned b1)
{
    asm volatile(
        "mma.sync.aligned.m16n8k16.row.col.f32.f16.f16.f32 "
        "{%0,%1,%2,%3}, {%4,%5,%6,%7}, {%8,%9}, {%0,%1,%2,%3};"
        : "+f"(c[0]), "+f"(c[1]), "+f"(c[2]), "+f"(c[3])
        : "r"(a0), "r"(a1), "r"(a2), "r"(a3), "r"(b0), "r"(b1));
}

// ---------------- K1: conv1 (f32x2) + conv2 (fp16 HMMA, W-split), 2 e's per CTA ----------------
// grid (E/2, T), block 128
__global__ __launch_bounds__(128) void k_conv(
    const float* __restrict__ points,
    const float* __restrict__ w1, const float* __restrict__ b1,
    const float* __restrict__ w2, const float* __restrict__ b2)
{
    // h1 transposed [p][ci], single fp16, row stride 18 halves (9 words)
    __shared__ __align__(16) __half h1h[520 * 18];
    __shared__ float pts[2][PP];
    __shared__ __align__(4) __half w2b[1280];   // [(co*5+s)*16 + ci]  fp16 big
    __shared__ __align__(4) __half w2r[1280];   // fp16 residual
    __shared__ float w1s[160];
    __shared__ float b1s[16], b2s[16];
    __shared__ float redw[4][16];

    const int tid = threadIdx.x;
    const int t = blockIdx.y, e0 = blockIdx.x * 2;

    unsigned* h1h32 = reinterpret_cast<unsigned*>(h1h);

    // ---- stage weights (once per CTA) + pts(e0) ----
    const float2* pin2 = reinterpret_cast<const float2*>(points + (size_t)(t * EE + e0) * PP * 2);
    #pragma unroll
    for (int j = 0; j < 4; j++) {
        int p = tid + j * 128;
        float2 v = pin2[p];
        pts[0][p] = v.x; pts[1][p] = v.y;
    }
    for (int i = tid; i < 160; i += 128) w1s[i] = w1[t * 160 + i];
    for (int i = tid; i < 1280; i += 128) {
        float v = w2[t * 1280 + i];
        int co = i / 80, rem = i % 80, ci = rem / 5, s = rem % 5;
        __half b = __float2half_rn(v);
        float r = v - __half2float(b);
        w2b[(co * 5 + s) * 16 + ci] = b;
        w2r[(co * 5 + s) * 16 + ci] = __float2half_rn(r);
    }
    if (tid < 16) { b1s[tid] = b1[t * 16 + tid]; b2s[tid] = b2[t * 16 + tid]; }
    __syncthreads();

    const int lane = tid & 31, wrp = tid >> 5;
    const int g = lane >> 2, tq = lane & 3;
    const float b2g = b2s[g], b2g8 = b2s[g + 8];

    #pragma unroll 1
    for (int sub = 0; sub < 2; sub++) {
        // ---- conv1 (packed f32x2, position pairs, co-pairs) -> h1 fp16 ----
        u64 xp[2][5], yp[2][5];
        #pragma unroll
        for (int pr = 0; pr < 2; pr++) {
            int pA = tid + (2 * pr) * 128;
            int pB = tid + (2 * pr + 1) * 128;
            int pAc = (pA < P1) ? pA : (P1 - 1);
            int pBc = (pB < P1) ? pB : (P1 - 1);
            #pragma unroll
            for (int k = 0; k < 5; k++) {
                xp[pr][k] = pack2(pts[0][pAc + k], pts[0][pBc + k]);
                yp[pr][k] = pack2(pts[1][pAc + k], pts[1][pBc + k]);
            }
        }
        // prefetch next e's points into regs (overlaps conv1 math)
        float2 pv[4];
        if (sub == 0) {
            const float2* pin2b = reinterpret_cast<const float2*>(
                points + (size_t)(t * EE + e0 + 1) * PP * 2);
            #pragma unroll
            for (int j = 0; j < 4; j++) pv[j] = pin2b[tid + j * 128];
        }

        const bool m1 = (tid + 384 < P1);
        #pragma unroll 1
        for (int cp = 0; cp < 8; cp++) {
            float wA[10], wB[10];
            #pragma unroll
            for (int q = 0; q < 10; q++) {
                wA[q] = w1s[(2 * cp) * 10 + q];
                wB[q] = w1s[(2 * cp + 1) * 10 + q];
            }
            float bbA = b1s[2 * cp], bbB = b1s[2 * cp + 1];
            u64 aA0 = pack2(bbA, bbA), aA1 = aA0;
            u64 aB0 = pack2(bbB, bbB), aB1 = aB0;
            #pragma unroll
            for (int k = 0; k < 5; k++) {
                u64 wa = pack2(wA[k], wA[k]);
                fma2(aA0, wa, xp[0][k]); fma2(aA1, wa, xp[1][k]);
                u64 wb = pack2(wB[k], wB[k]);
                fma2(aB0, wb, xp[0][k]); fma2(aB1, wb, xp[1][k]);
            }
            #pragma unroll
            for (int k = 0; k < 5; k++) {
                u64 wa = pack2(wA[5 + k], wA[5 + k]);
                fma2(aA0, wa, yp[0][k]); fma2(aA1, wa, yp[1][k]);
                u64 wb = pack2(wB[5 + k], wB[5 + k]);
                fma2(aB0, wb, yp[0][k]); fma2(aB1, wb, yp[1][k]);
            }
            float vA[4], vB[4];
            unpack2(aA0, vA[0], vA[1]); unpack2(aA1, vA[2], vA[3]);
            unpack2(aB0, vB[0], vB[1]); unpack2(aB1, vB[2], vB[3]);
            #pragma unroll
            for (int j = 0; j < 4; j++) {
                if (j == 3 && !m1) break;
                int p = tid + j * 128;
                float a = fmaxf(vA[j], 0.f), b = fmaxf(vB[j], 0.f);
                __half2 hv = __floats2half2_rn(a, b);   // .x (low) = a = even co
                h1h32[p * 9 + cp] = *reinterpret_cast<unsigned*>(&hv);
            }
        }
        __syncthreads();   // h1 ready; all pts reads complete

        // commit prefetched next-e points (safe: pts reads done)
        if (sub == 0) {
            #pragma unroll
            for (int j = 0; j < 4; j++) {
                int p = tid + j * 128;
                pts[0][p] = pv[j].x; pts[1][p] = pv[j].y;
            }
        }

        // ---- conv2 via fp16 HMMA (2 terms: hb*Wb + hb*Wr) ----
        float acc[16][4];
        #pragma unroll
        for (int i = 0; i < 16; i++) {
            acc[i][0] = 0.f; acc[i][1] = 0.f; acc[i][2] = 0.f; acc[i][3] = 0.f;
        }
        const unsigned* w2b32 = reinterpret_cast<const unsigned*>(w2b);
        const unsigned* w2r32 = reinterpret_cast<const unsigned*>(w2r);

        #pragma unroll
        for (int s = 0; s < 5; s++) {
            const int awl = (g * 5 + s) * 8 + tq;
            const int awh = ((g + 8) * 5 + s) * 8 + tq;
            unsigned ab0 = w2b32[awl],     ab1 = w2b32[awh];
            unsigned ab2 = w2b32[awl + 4], ab3 = w2b32[awh + 4];
            unsigned ar0 = w2r32[awl],     ar1 = w2r32[awh];
            unsigned ar2 = w2r32[awl + 4], ar3 = w2r32[awh + 4];
            #pragma unroll
            for (int i = 0; i < 16; i++) {
                int nb = wrp + 4 * i;
                if (nb >= 63) break;
                int pw = (nb * 8 + g + s) * 9 + tq;
                unsigned bb0 = h1h32[pw], bb1 = h1h32[pw + 4];
                mma_f16(acc[i], ab0, ab1, ab2, ab3, bb0, bb1);
                mma_f16(acc[i], ar0, ar1, ar2, ar3, bb0, bb1);
            }
        }

        // ---- epilogue: bias + relu per position, point-sum ----
        float sg = 0.f, sg8 = 0.f;
        #pragma unroll
        for (int i = 0; i < 16; i++) {
            int nb = wrp + 4 * i;
            if (nb >= 63) break;
            sg  += fmaxf(acc[i][0] + b2g, 0.f)  + fmaxf(acc[i][1] + b2g, 0.f);
            sg8 += fmaxf(acc[i][2] + b2g8, 0.f) + fmaxf(acc[i][3] + b2g8, 0.f);
        }
        sg  += __shfl_xor_sync(0xffffffffu, sg, 1);
        sg  += __shfl_xor_sync(0xffffffffu, sg, 2);
        sg8 += __shfl_xor_sync(0xffffffffu, sg8, 1);
        sg8 += __shfl_xor_sync(0xffffffffu, sg8, 2);
        if (tq == 0) { redw[wrp][g] = sg; redw[wrp][g + 8] = sg8; }
        __syncthreads();   // redw ready; conv2 done reading h1; pts(e1) visible
        if (tid < 16)
            d_elem[(size_t)(t * EE + e0 + sub) * 16 + tid] =
                redw[0][tid] + redw[1][tid] + redw[2][tid] + redw[3][tid];
    }
}

// ---------------- K2: s0 partials (+zero gmax)  grid (32, T), block 256 ----------------
__global__ __launch_bounds__(256) void k_s0p() {
    const int t = blockIdx.y, chunk = blockIdx.x, tid = threadIdx.x;
    const int d = tid & 15, grp = tid >> 4;   // 16 groups x 4 e's
    const int e0 = chunk * 64;
    float acc = 0.f;
    #pragma unroll
    for (int i = 0; i < 4; i++)
        acc += d_elem[(size_t)(t * EE + e0 + grp + 16 * i) * 16 + d];
    __shared__ float r[256];
    r[tid] = acc; __syncthreads();
    if (tid < 128) r[tid] += r[tid + 128];
    __syncthreads();
    if (tid < 64) r[tid] += r[tid + 64];
    __syncthreads();
    if (tid < 32) r[tid] += r[tid + 32];
    __syncthreads();
    if (tid < 16) d_s0p[(t * 32 + chunk) * 16 + tid] = r[tid] + r[tid + 16];
    if (chunk == 0 && tid < 128) d_gmax[t * 128 + tid] = 0;
}

// ---------------- K3: layer1 -> d_g1 + s1 partials  grid (128, T), block 256 ----------------
__global__ __launch_bounds__(256) void k_l1(
    const float* __restrict__ A1, const float* __restrict__ B1)
{
    __shared__ float C1s[16][128];
    __shared__ float elems[16][16];
    __shared__ float r[256];
    __shared__ float s0s[16];

    const int tid = threadIdx.x, t = blockIdx.y, chunk = blockIdx.x;
    const int e0 = chunk * 16;
    const int h = tid & 127, half = tid >> 7;

    elems[tid >> 4][tid & 15] = d_elem[(size_t)(t * EE + e0) * 16 + tid];
    for (int i = tid; i < 2048; i += 256)
        C1s[i >> 7][i & 127] = A1[t * 2048 + i] - B1[t * 2048 + i];
    if (tid < 16) {
        float s = 0.f;
        #pragma unroll
        for (int b = 0; b < 32; b++) s += d_s0p[(t * 32 + b) * 16 + tid];
        s0s[tid] = s;
    }
    __syncthreads();

    float c1r[16];
    #pragma unroll
    for (int d = 0; d < 16; d++) c1r[d] = C1s[d][h];
    float sbl1 = 0.f;
    #pragma unroll
    for (int d = 0; d < 16; d++)
        sbl1 = fmaf(s0s[d], B1[t * 2048 + d * 128 + h], sbl1);

    float accs = 0.f;
    const int eib = half * 8;
    #pragma unroll
    for (int ei = 0; ei < 8; ei++) {
        float v = sbl1;
        #pragma unroll
        for (int d = 0; d < 16; d++) v = fmaf(elems[eib + ei][d], c1r[d], v);
        v = fmaxf(v, 0.f);
        d_g1[(size_t)(t * EE + e0 + eib + ei) * 128 + h] = v;
        accs += v;
    }
    r[tid] = accs;
    __syncthreads();
    if (tid < 128)
        d_s1p[(t * 128 + chunk) * 128 + tid] = r[tid] + r[tid + 128];
}

// ---------------- K3b: combine s1 partials  grid (T), block 512 ----------------
__global__ __launch_bounds__(512) void k_s1c() {
    const int t = blockIdx.x, tid = threadIdx.x;
    const int h = tid & 127, q = tid >> 7;   // 4 groups x 32 partials
    float s = 0.f;
    #pragma unroll 8
    for (int i = 0; i < 32; i++)
        s += d_s1p[(t * 128 + q * 32 + i) * 128 + h];
    __shared__ float r[512];
    r[tid] = s; __syncthreads();
    if (tid < 128)
        d_s1[t * 128 + tid] = r[tid] + r[tid + 128] + r[tid + 256] + r[tid + 384];
}

// ---------------- K4: layer2 GEMM + max  grid (64, T), block 256 (32 e's/block) ----------------
__global__ __launch_bounds__(256) void k_l2(
    const float* __restrict__ A2, const float* __restrict__ B2)
{
    __shared__ __align__(8) float g1T[128][34];   // [feature d][ei 0..31]
    __shared__ float C2q[2][16][128];
    __shared__ float r[256];
    __shared__ float s1s[128];

    const int tid = threadIdx.x, t = blockIdx.y, chunk = blockIdx.x;
    const int e0 = chunk * 32;
    const int h = tid & 127, half = tid >> 7;
    const int tb = t * 16384;

    // prefetch first C2 slab early
    float pa_[8], pb_[8];
    #pragma unroll
    for (int k = 0; k < 8; k++) {
        int idx = tid + k * 256;
        pa_[k] = A2[tb + idx];
        pb_[k] = B2[tb + idx];
    }

    // s1 (pre-combined)
    if (tid < 128) s1s[tid] = d_s1[t * 128 + tid];

    // g1 tile load (transposed into smem)
    for (int i = tid; i < 4096; i += 256) {
        int ei = i >> 7, hh = i & 127;
        g1T[hh][ei] = d_g1[(size_t)(t * EE + e0 + ei) * 128 + hh];
    }
    __syncthreads();

    u64 acc2[8];
    #pragma unroll
    for (int pr = 0; pr < 8; pr++) acc2[pr] = 0ull;
    float sbp = 0.f;

    #pragma unroll 1
    for (int q = 0; q < 8; q++) {
        const int buf = q & 1;
        #pragma unroll
        for (int k = 0; k < 8; k++) {
            int d = 2 * k + half;
            sbp = fmaf(s1s[q * 16 + d], pb_[k], sbp);
            C2q[buf][d][h] = pa_[k] - pb_[k];
        }
        __syncthreads();
        if (q < 7) {
            const int base = tb + (q + 1) * 16 * 128;
            #pragma unroll
            for (int k = 0; k < 8; k++) {
                int idx = tid + k * 256;
                pa_[k] = A2[base + idx];
                pb_[k] = B2[base + idx];
            }
        }
        #pragma unroll 4
        for (int dd = 0; dd < 16; dd++) {
            float c = C2q[buf][dd][h];
            u64 cp = pack2(c, c);
            const u64* grow = reinterpret_cast<const u64*>(&g1T[q * 16 + dd][half * 16]);
            #pragma unroll
            for (int pr = 0; pr < 8; pr++) fma2(acc2[pr], grow[pr], cp);
        }
        __syncthreads();
    }

    // combine sb halves (even/odd d parity)
    r[tid] = sbp;
    __syncthreads();
    const float sb = r[h] + r[h + 128];

    float m = 0.f;   // relu floor == max identity
    #pragma unroll
    for (int pr = 0; pr < 8; pr++) {
        float a, b;
        unpack2(acc2[pr], a, b);
        m = fmaxf(m, fmaxf(a + sb, b + sb));
    }
    atomicMax(&d_gmax[t * 128 + h], __float_as_int(m));
}

// ---------------- K5: gf + final matmul partials  grid 8, block 256 ----------------
__global__ __launch_bounds__(256) void k_gfw(const float* __restrict__ Aout,
                                             const float* __restrict__ Wm)
{
    __shared__ float gv[512];
    __shared__ float gfs[64];
    __shared__ float r[256];
    const int tid = threadIdx.x, blk = blockIdx.x;

    for (int i = tid; i < 512; i += 256) gv[i] = __int_as_float(d_gmax[i]);
    __syncthreads();

    const int j = tid >> 2, sub = tid & 3;
    const int gi = blk * 64 + j;          // global gf index = t*128 + o
    const int t2 = gi >> 7, o = gi & 127;
    float a = 0.f;
    #pragma unroll 4
    for (int k = 0; k < 32; k++)
        a = fmaf(gv[t2 * 128 + sub * 32 + k],
                 Aout[t2 * 16384 + (sub * 32 + k) * 128 + o], a);
    r[tid] = a;
    __syncthreads();
    if (sub == 0) gfs[j] = r[tid] + r[tid + 1] + r[tid + 2] + r[tid + 3];
    __syncthreads();

    float acc = 0.f;
    const int i0 = blk * 64;
    #pragma unroll 8
    for (int i = 0; i < 64; i++)
        acc = fmaf(gfs[i], Wm[(i0 + i) * 256 + tid], acc);
    d_fpart[blk * 256 + tid] = acc;
}

// ---------------- K6: combine  grid 1, block 256 ----------------
__global__ void k_fin2(const float* __restrict__ bm, float* __restrict__ out) {
    const int tid = threadIdx.x;
    float a = bm[tid];
    #pragma unroll
    for (int b = 0; b < 8; b++) a += d_fpart[b * 256 + tid];
    out[tid] = a;
}

// ---------------- launch ----------------
extern "C" void kernel_launch(void* const* d_in, const int* in_sizes, int n_in,
                              void* d_out, int out_size)
{
    const float* points = (const float*)d_in[0];
    const float* w1     = (const float*)d_in[1];
    const float* b1     = (const float*)d_in[2];
    const float* w2     = (const float*)d_in[3];
    const float* b2     = (const float*)d_in[4];
    const float* A1     = (const float*)d_in[5];
    const float* B1     = (const float*)d_in[6];
    const float* A2     = (const float*)d_in[7];
    const float* B2     = (const float*)d_in[8];
    const float* Aout   = (const float*)d_in[9];
    const float* Wm     = (const float*)d_in[10];
    const float* bm     = (const float*)d_in[11];
    float* out = (float*)d_out;

    k_conv<<<dim3(EE / 2, TT), 128>>>(points, w1, b1, w2, b2);
    k_s0p<<<dim3(32, TT), 256>>>();
    k_l1<<<dim3(128, TT), 256>>>(A1, B1);
    k_s1c<<<TT, 512>>>();
    k_l2<<<dim3(64, TT), 256>>>(A2, B2);
    k_gfw<<<8, 256>>>(Aout, Wm);
    k_fin2<<<1, 256>>>(bm, out);
}